// round 11
// baseline (speedup 1.0000x reference)
#include <cuda_runtime.h>
#include <cuda_bf16.h>
#include <math.h>
#include <cstdint>

// Problem constants
#define Nn 4
#define Cc 64
#define Hh 128
#define Ww 128
#define HW (Hh*Ww)           // 16384
#define Kk 9
#define COUT 64
#define CK (Cc*Kk)           // 576
#define OFFCH 18
#define MASKCH 9
#define OMPAD 32

// Scratch (device globals -- allocation-free per harness rules)
__device__ float g_off [Nn*OFFCH*HW];
__device__ float g_mask[Nn*MASKCH*HW];
__device__ unsigned short g_whi[Kk*COUT*Cc];   // w_dcn k-major bf16 hi [k][o][c]
__device__ unsigned short g_wlo[Kk*COUT*Cc];
__device__ unsigned short g_omhi[Kk*OMPAD*Cc];
__device__ unsigned short g_omlo[Kk*OMPAD*Cc];

// ---------------------------------------------------------------------------
// Warp-MMA helpers
// ---------------------------------------------------------------------------
__device__ __forceinline__ uint32_t smem_u32(const void* p) {
    uint32_t a;
    asm("{ .reg .u64 t; cvta.to.shared.u64 t, %1; cvt.u32.u64 %0, t; }"
        : "=r"(a) : "l"(p));
    return a;
}
__device__ __forceinline__ void ldsm_x4(uint32_t* r, uint32_t addr) {
    asm volatile("ldmatrix.sync.aligned.m8n8.x4.shared.b16 {%0,%1,%2,%3}, [%4];"
        : "=r"(r[0]), "=r"(r[1]), "=r"(r[2]), "=r"(r[3]) : "r"(addr));
}
__device__ __forceinline__ void ldsm_x4_t(uint32_t* r, uint32_t addr) {
    asm volatile("ldmatrix.sync.aligned.m8n8.x4.trans.shared.b16 {%0,%1,%2,%3}, [%4];"
        : "=r"(r[0]), "=r"(r[1]), "=r"(r[2]), "=r"(r[3]) : "r"(addr));
}
__device__ __forceinline__ void mma_bf16(float* c, const uint32_t* a, const uint32_t* b) {
    asm volatile(
        "mma.sync.aligned.m16n8k16.row.col.f32.bf16.bf16.f32 "
        "{%0,%1,%2,%3}, {%4,%5,%6,%7}, {%8,%9}, {%0,%1,%2,%3};"
        : "+f"(c[0]), "+f"(c[1]), "+f"(c[2]), "+f"(c[3])
        : "r"(a[0]), "r"(a[1]), "r"(a[2]), "r"(a[3]), "r"(b[0]), "r"(b[1]));
}
#define BAR_SYNC(id, cnt) asm volatile("bar.sync %0, %1;" :: "r"(id), "r"(cnt) : "memory")

// fast 2-way bf16 split: hi = RN(v), lo = RN(v - float(hi))
__device__ __forceinline__ void split_pack(float v0, float v1,
                                           uint32_t& hi2, uint32_t& lo2) {
    asm("cvt.rn.bf16x2.f32 %0, %2, %1;" : "=r"(hi2) : "f"(v0), "f"(v1));
    const float h0 = __uint_as_float(hi2 << 16);
    const float h1 = __uint_as_float(hi2 & 0xFFFF0000u);
    const float l0 = v0 - h0;
    const float l1 = v1 - h1;
    asm("cvt.rn.bf16x2.f32 %0, %2, %1;" : "=r"(lo2) : "f"(l0), "f"(l1));
}

// bilinear sampling descriptor (per pixel, per tap)
struct Desc { int i00, i01, i10, i11; float w00, w01, w10, w11; };

__device__ __forceinline__ Desc make_sdesc(int n, int j, int pq) {
    Desc d;
    const int p = pq >> 7;
    const int q = pq & (Ww - 1);
    const float offy = g_off[((size_t)n * OFFCH + 2 * j)     * HW + pq];
    const float offx = g_off[((size_t)n * OFFCH + 2 * j + 1) * HW + pq];
    const float msk  = g_mask[((size_t)n * MASKCH + j) * HW + pq];
    const float y  = (float)(p - 1 + j / 3) + offy;
    const float xs = (float)(q - 1 + j % 3) + offx;
    const float y0f = floorf(y), x0f = floorf(xs);
    const float wy1 = y - y0f,   wx1 = xs - x0f;
    const int   y0 = (int)y0f,   x0 = (int)x0f;
    const int   y1 = y0 + 1,     x1 = x0 + 1;
    d.w00 = (1.f - wy1) * (1.f - wx1) * msk;
    d.w01 = (1.f - wy1) * wx1 * msk;
    d.w10 = wy1 * (1.f - wx1) * msk;
    d.w11 = wy1 * wx1 * msk;
    if (!(((unsigned)y0 < (unsigned)Hh) & ((unsigned)x0 < (unsigned)Ww))) d.w00 = 0.f;
    if (!(((unsigned)y0 < (unsigned)Hh) & ((unsigned)x1 < (unsigned)Ww))) d.w01 = 0.f;
    if (!(((unsigned)y1 < (unsigned)Hh) & ((unsigned)x0 < (unsigned)Ww))) d.w10 = 0.f;
    if (!(((unsigned)y1 < (unsigned)Hh) & ((unsigned)x1 < (unsigned)Ww))) d.w11 = 0.f;
    const int y0c = min(max(y0, 0), Hh - 1);
    const int y1c = min(max(y1, 0), Hh - 1);
    const int x0c = min(max(x0, 0), Ww - 1);
    const int x1c = min(max(x1, 0), Ww - 1);
    d.i00 = y0c * Ww + x0c;  d.i01 = y0c * Ww + x1c;
    d.i10 = y1c * Ww + x0c;  d.i11 = y1c * Ww + x1c;
    return d;
}
__device__ __forceinline__ float samp(const Desc& d, const float* xc) {
    return d.w00 * __ldg(xc + d.i00) + d.w01 * __ldg(xc + d.i01)
         + d.w10 * __ldg(xc + d.i10) + d.w11 * __ldg(xc + d.i11);
}

#define PITCH  144     // W rows: 128B + 16B skew
#define TPITCH 272     // S^T rows (128 px): 256B + 16B skew

// Per-group SMEM layout (two independent groups per CTA)
#define G_SHI 0                        // 64*272 = 17408
#define G_SLO (G_SHI + 64*TPITCH)
#define G_WHI (G_SLO + 64*TPITCH)      // 64*144 = 9216
#define G_WLO (G_WHI + 64*PITCH)
#define GRP_BYTES (G_WLO + 64*PITCH)   // 53248
#define T_TOTAL (2 * GRP_BYTES)        // 106496 -> 2 CTAs/SM

// ---------------------------------------------------------------------------
// Kernel W-prep (unchanged)
// ---------------------------------------------------------------------------
#define WPREP_DCN (Kk*COUT*Cc)
#define WPREP_TOT (WPREP_DCN + Kk*OMPAD*Cc)
__global__ __launch_bounds__(256) void wprep_kernel(
    const float* __restrict__ w_dcn, const float* __restrict__ w_om)
{
    const int e = blockIdx.x * 256 + threadIdx.x;
    if (e >= WPREP_TOT) return;
    if (e < WPREP_DCN) {
        const int k = e / (COUT * Cc);
        const int r = e - k * (COUT * Cc);
        const int o = r >> 6;
        const int c = r & 63;
        const float w = __ldg(w_dcn + (size_t)o * CK + c * Kk + k);
        const __nv_bfloat16 hi = __float2bfloat16(w);
        g_whi[e] = __bfloat16_as_ushort(hi);
        g_wlo[e] = __bfloat16_as_ushort(__float2bfloat16(w - __bfloat162float(hi)));
    } else {
        const int e2 = e - WPREP_DCN;
        const int k = e2 >> 11;
        const int r = e2 & 2047;
        const int o = r >> 6;
        const int c = r & 63;
        float w = 0.f;
        if (o < 27) w = __ldg(w_om + (size_t)o * CK + c * Kk + k);
        const __nv_bfloat16 hi = __float2bfloat16(w);
        g_omhi[e2] = __bfloat16_as_ushort(hi);
        g_omlo[e2] = __bfloat16_as_ushort(__float2bfloat16(w - __bfloat162float(hi)));
    }
}

// ---------------------------------------------------------------------------
// Kernel A (HMMA): offset/mask conv. (round-7/9 version, ~36us)
// ---------------------------------------------------------------------------
#define CPITCH 144
__global__ __launch_bounds__(256, 3) void convA_mma_kernel(
    const float* __restrict__ x,
    const float* __restrict__ b_om)
{
    __shared__ char csm[128 * CPITCH * 2 + 32 * CPITCH * 2];  // 46080 B
#define CSHI 0
#define CSLO (128 * CPITCH)
#define CWHI (2 * 128 * CPITCH)
#define CWLO (2 * 128 * CPITCH + 32 * CPITCH)
    const uint32_t sbase = smem_u32(csm);
    const int n   = blockIdx.z;
    const int p   = blockIdx.x;
    const int tid = threadIdx.x;
    const int wid = tid >> 5;
    const int lid = tid & 31;

    const float* xn = x + (size_t)n * Cc * HW;

    float acc[4][4];
#pragma unroll
    for (int t = 0; t < 4; t++)
#pragma unroll
        for (int i = 0; i < 4; i++) acc[t][i] = 0.f;

    const int a_row  = wid * 16 + (((lid >> 3) & 1) << 3) + (lid & 7);
    const int a_cg   = (lid >> 4);
    const int b_oofs = ((lid >> 4) << 3) + (lid & 7);
    const int b_cg   = ((lid >> 3) & 1);

    const int g_row  = tid & 127;
    const int g_half = tid >> 7;

    for (int j = 0; j < 9; j++) {
        __syncthreads();
        {
            const uint32_t* whp = (const uint32_t*)g_omhi + j * 1024;
            const uint32_t* wlp = (const uint32_t*)g_omlo + j * 1024;
#pragma unroll
            for (int i = 0; i < 4; i++) {
                const int e  = tid + i * 256;
                const int o  = e >> 5;
                const int cg = e & 31;
                const uint32_t off = o * CPITCH + cg * 4;
                *(uint32_t*)(csm + CWHI + off) = __ldg(whp + e);
                *(uint32_t*)(csm + CWLO + off) = __ldg(wlp + e);
            }
        }
        {
            const int y  = p + j / 3 - 1;
            const int xc = g_row + j % 3 - 1;
            const bool ok = ((unsigned)y < (unsigned)Hh) & ((unsigned)xc < (unsigned)Ww);
            const float* bp = xn + (size_t)g_half * 32 * HW + y * Ww + xc;
            uint32_t soff = g_row * CPITCH + (g_half * 16) * 4;
#pragma unroll
            for (int i = 0; i < 16; i++) {
                const float v0 = ok ? __ldg(bp)      : 0.f;
                const float v1 = ok ? __ldg(bp + HW) : 0.f;
                bp += 2 * HW;
                uint32_t hi2, lo2;
                split_pack(v0, v1, hi2, lo2);
                *(uint32_t*)(csm + CSHI + soff) = hi2;
                *(uint32_t*)(csm + CSLO + soff) = lo2;
                soff += 4;
            }
        }
        __syncthreads();

#pragma unroll
        for (int ks = 0; ks < 4; ks++) {
            uint32_t ahi[4], alo[4];
            const uint32_t aoff = a_row * CPITCH + (ks * 2 + a_cg) * 16;
            ldsm_x4(ahi, sbase + CSHI + aoff);
            ldsm_x4(alo, sbase + CSLO + aoff);
#pragma unroll
            for (int nt = 0; nt < 2; nt++) {
                uint32_t bh[4], bl[4];
                const uint32_t boff = (nt * 16 + b_oofs) * CPITCH + (ks * 2 + b_cg) * 16;
                ldsm_x4(bh, sbase + CWHI + boff);
                ldsm_x4(bl, sbase + CWLO + boff);
                mma_bf16(acc[nt * 2],     ahi, bh);
                mma_bf16(acc[nt * 2 + 1], ahi, bh + 2);
                mma_bf16(acc[nt * 2],     ahi, bl);
                mma_bf16(acc[nt * 2 + 1], ahi, bl + 2);
                mma_bf16(acc[nt * 2],     alo, bh);
                mma_bf16(acc[nt * 2 + 1], alo, bh + 2);
            }
        }
    }

    const int px = p * Ww + wid * 16 + (lid >> 2);
    float* offp = g_off  + (size_t)n * OFFCH  * HW;
    float* mskp = g_mask + (size_t)n * MASKCH * HW;
#pragma unroll
    for (int t = 0; t < 4; t++) {
        const int o0 = t * 8 + 2 * (lid & 3);
#pragma unroll
        for (int i = 0; i < 4; i++) {
            const int o  = o0 + (i & 1);
            const int pq = px + (i >> 1) * 8;
            if (o >= 27) continue;
            const float v = acc[t][i] + __ldg(b_om + o);
            if (o < OFFCH) offp[(size_t)o * HW + pq] = v;
            else           mskp[(size_t)(o - OFFCH) * HW + pq] = 1.f / (1.f + expf(-v));
        }
    }
}

// ---------------------------------------------------------------------------
// Kernel BC: fused deform-sample + HMMA GEMM.
// Two INDEPENDENT 128-px groups per CTA (4 warps each, named barriers) ->
// 4 free-running gather/MMA pipelines per SM for pipe mixing.
// ---------------------------------------------------------------------------
__global__ __launch_bounds__(256, 2) void fusedBC_mma_kernel(
    const float* __restrict__ x,
    float* __restrict__ out)
{
    extern __shared__ char smem[];
    const int tid  = threadIdx.x;
    const int grp  = tid >> 7;             // 0/1
    const int gtid = tid & 127;
    const int gwid = gtid >> 5;            // 0..3 (warp within group)
    const int lid  = tid & 31;
    const int barid = grp + 1;             // named barrier 1 or 2

    char* gs = smem + grp * GRP_BYTES;
    const uint32_t sbase = smem_u32(gs);

    const int n  = blockIdx.z;
    const int j0 = blockIdx.x * 256 + grp * 128;  // this group's 128 pixels

    const float* xn = x + (size_t)n * Cc * HW;

    float acc[2][8][4];
#pragma unroll
    for (int m = 0; m < 2; m++)
#pragma unroll
        for (int t = 0; t < 8; t++)
#pragma unroll
            for (int i = 0; i < 4; i++) acc[m][t][i] = 0.f;

    // A-frag ldsm.trans components
    const int a_ckb = (lid & 7) + (((lid >> 3) & 2) << 2);
    const int a_px8 = (((lid >> 3) & 1) << 3);
    // B-frag components
    const int b_oofs = ((lid >> 4) << 3) + (lid & 7);
    const int b_cg   = ((lid >> 3) & 1);

    // gather mapping within group: 64 pixel-pairs x 2 channel-halves
    const int pp  = gtid & 63;             // pixels 2pp, 2pp+1 (group-local)
    const int ckh = gtid >> 6;             // 0/1 -> channels ckh*32..+31

    for (int j = 0; j < 9; j++) {
        BAR_SYNC(barid, 128);              // prev chunk's reads done
        // stage this group's W chunk: 2048 u32 per buffer, 128 threads
        {
            const uint32_t* whp = (const uint32_t*)g_whi + j * 2048;
            const uint32_t* wlp = (const uint32_t*)g_wlo + j * 2048;
#pragma unroll
            for (int i = 0; i < 16; i++) {
                const int e  = gtid + i * 128;
                const int o  = e >> 5;
                const int cg = e & 31;
                const uint32_t off = o * PITCH + cg * 4;
                *(uint32_t*)(gs + G_WHI + off) = __ldg(whp + e);
                *(uint32_t*)(gs + G_WLO + off) = __ldg(wlp + e);
            }
        }
        // private descriptors, hoisted over the 32-channel walk
        const Desc d0 = make_sdesc(n, j, j0 + 2 * pp);
        const Desc d1 = make_sdesc(n, j, j0 + 2 * pp + 1);
        {
            const float* xc = xn + (size_t)(ckh * 32) * HW;
            uint32_t soff = (ckh * 32) * TPITCH + pp * 4;
#pragma unroll 8
            for (int i = 0; i < 32; i++) {
                const float v0 = samp(d0, xc);
                const float v1 = samp(d1, xc);
                xc += HW;
                uint32_t hi2, lo2;
                split_pack(v0, v1, hi2, lo2);
                *(uint32_t*)(gs + G_SHI + soff) = hi2;
                *(uint32_t*)(gs + G_SLO + soff) = lo2;
                soff += TPITCH;
            }
        }
        BAR_SYNC(barid, 128);              // tiles ready

#pragma unroll
        for (int ks = 0; ks < 4; ks++) {
            uint32_t ahi[2][4], alo[2][4];
#pragma unroll
            for (int m = 0; m < 2; m++) {
                const uint32_t aoff = (ks * 16 + a_ckb) * TPITCH
                                    + (gwid * 32 + m * 16 + a_px8) * 2;
                ldsm_x4_t(ahi[m], sbase + G_SHI + aoff);
                ldsm_x4_t(alo[m], sbase + G_SLO + aoff);
            }
#pragma unroll
            for (int nt = 0; nt < 4; nt++) {
                uint32_t bh[4], bl[4];
                const uint32_t boff = (nt * 16 + b_oofs) * PITCH + (ks * 2 + b_cg) * 16;
                ldsm_x4(bh, sbase + G_WHI + boff);
                ldsm_x4(bl, sbase + G_WLO + boff);
#pragma unroll
                for (int m = 0; m < 2; m++) {
                    mma_bf16(acc[m][nt * 2],     ahi[m], bh);
                    mma_bf16(acc[m][nt * 2 + 1], ahi[m], bh + 2);
                    mma_bf16(acc[m][nt * 2],     ahi[m], bl);
                    mma_bf16(acc[m][nt * 2 + 1], ahi[m], bl + 2);
                    mma_bf16(acc[m][nt * 2],     alo[m], bh);
                    mma_bf16(acc[m][nt * 2 + 1], alo[m], bh + 2);
                }
            }
        }
    }

    // Epilogue: D fragments -> out[n][o][pq]
    float* op = out + (size_t)n * COUT * HW;
#pragma unroll
    for (int m = 0; m < 2; m++) {
        const int px = j0 + gwid * 32 + m * 16 + (lid >> 2);
#pragma unroll
        for (int t = 0; t < 8; t++) {
            const int o0 = t * 8 + 2 * (lid & 3);
            op[(size_t)o0       * HW + px    ] = acc[m][t][0];
            op[(size_t)(o0 + 1) * HW + px    ] = acc[m][t][1];
            op[(size_t)o0       * HW + px + 8] = acc[m][t][2];
            op[(size_t)(o0 + 1) * HW + px + 8] = acc[m][t][3];
        }
    }
}

// ---------------------------------------------------------------------------
extern "C" void kernel_launch(void* const* d_in, const int* in_sizes, int n_in,
                              void* d_out, int out_size)
{
    const float* x     = (const float*)d_in[0];  // (4,64,128,128)
    const float* w_om  = (const float*)d_in[1];  // (27,64,3,3)
    const float* b_om  = (const float*)d_in[2];  // (27,)
    const float* w_dcn = (const float*)d_in[3];  // (64,64,3,3)
    float* out = (float*)d_out;                  // (4,64,128,128)

    wprep_kernel<<<(WPREP_TOT + 255) / 256, 256>>>(w_dcn, w_om);

    dim3 gA(Hh, 1, Nn);                          // 512 blocks
    convA_mma_kernel<<<gA, 256>>>(x, b_om);

    cudaFuncSetAttribute(fusedBC_mma_kernel,
                         cudaFuncAttributeMaxDynamicSharedMemorySize, T_TOTAL);
    dim3 gBC(HW / 256, 1, Nn);                   // 64 x 4 = 256 blocks
    fusedBC_mma_kernel<<<gBC, 256, T_TOTAL>>>(x, out);
}

// round 13
// speedup vs baseline: 1.6986x; 1.6986x over previous
#include <cuda_runtime.h>
#include <cuda_bf16.h>
#include <math.h>
#include <cstdint>

// Problem constants
#define Nn 4
#define Cc 64
#define Hh 128
#define Ww 128
#define HW (Hh*Ww)           // 16384
#define Kk 9
#define COUT 64
#define CK (Cc*Kk)           // 576
#define OFFCH 18
#define MASKCH 9
#define OMPAD 32

// Scratch (device globals -- allocation-free per harness rules)
__device__ float g_off [Nn*OFFCH*HW];
__device__ float g_mask[Nn*MASKCH*HW];
__device__ unsigned short g_whi[Kk*COUT*Cc];   // w_dcn k-major bf16 hi [k][o][c]
__device__ unsigned short g_wlo[Kk*COUT*Cc];
__device__ unsigned short g_omhi[Kk*OMPAD*Cc];
__device__ unsigned short g_omlo[Kk*OMPAD*Cc];

// ---------------------------------------------------------------------------
// Warp-MMA helpers
// ---------------------------------------------------------------------------
__device__ __forceinline__ uint32_t smem_u32(const void* p) {
    uint32_t a;
    asm("{ .reg .u64 t; cvta.to.shared.u64 t, %1; cvt.u32.u64 %0, t; }"
        : "=r"(a) : "l"(p));
    return a;
}
__device__ __forceinline__ void ldsm_x4(uint32_t* r, uint32_t addr) {
    asm volatile("ldmatrix.sync.aligned.m8n8.x4.shared.b16 {%0,%1,%2,%3}, [%4];"
        : "=r"(r[0]), "=r"(r[1]), "=r"(r[2]), "=r"(r[3]) : "r"(addr));
}
__device__ __forceinline__ void ldsm_x4_t(uint32_t* r, uint32_t addr) {
    asm volatile("ldmatrix.sync.aligned.m8n8.x4.trans.shared.b16 {%0,%1,%2,%3}, [%4];"
        : "=r"(r[0]), "=r"(r[1]), "=r"(r[2]), "=r"(r[3]) : "r"(addr));
}
__device__ __forceinline__ void mma_bf16(float* c, const uint32_t* a, const uint32_t* b) {
    asm volatile(
        "mma.sync.aligned.m16n8k16.row.col.f32.bf16.bf16.f32 "
        "{%0,%1,%2,%3}, {%4,%5,%6,%7}, {%8,%9}, {%0,%1,%2,%3};"
        : "+f"(c[0]), "+f"(c[1]), "+f"(c[2]), "+f"(c[3])
        : "r"(a[0]), "r"(a[1]), "r"(a[2]), "r"(a[3]), "r"(b[0]), "r"(b[1]));
}
#define BAR_SYNC(id, cnt)   asm volatile("bar.sync %0, %1;"   :: "r"(id), "r"(cnt) : "memory")
#define BAR_ARRIVE(id, cnt) asm volatile("bar.arrive %0, %1;" :: "r"(id), "r"(cnt) : "memory")

// fast 2-way bf16 split: hi = RN(v), lo = RN(v - float(hi))
__device__ __forceinline__ void split_pack(float v0, float v1,
                                           uint32_t& hi2, uint32_t& lo2) {
    asm("cvt.rn.bf16x2.f32 %0, %2, %1;" : "=r"(hi2) : "f"(v0), "f"(v1));
    const float h0 = __uint_as_float(hi2 << 16);
    const float h1 = __uint_as_float(hi2 & 0xFFFF0000u);
    const float l0 = v0 - h0;
    const float l1 = v1 - h1;
    asm("cvt.rn.bf16x2.f32 %0, %2, %1;" : "=r"(lo2) : "f"(l0), "f"(l1));
}

// bilinear sampling descriptor (per pixel, per tap)
struct Desc { int i00, i01, i10, i11; float w00, w01, w10, w11; };

__device__ __forceinline__ Desc make_sdesc(int n, int j, int pq) {
    Desc d;
    const int p = pq >> 7;
    const int q = pq & (Ww - 1);
    const float offy = g_off[((size_t)n * OFFCH + 2 * j)     * HW + pq];
    const float offx = g_off[((size_t)n * OFFCH + 2 * j + 1) * HW + pq];
    const float msk  = g_mask[((size_t)n * MASKCH + j) * HW + pq];
    const float y  = (float)(p - 1 + j / 3) + offy;
    const float xs = (float)(q - 1 + j % 3) + offx;
    const float y0f = floorf(y), x0f = floorf(xs);
    const float wy1 = y - y0f,   wx1 = xs - x0f;
    const int   y0 = (int)y0f,   x0 = (int)x0f;
    const int   y1 = y0 + 1,     x1 = x0 + 1;
    d.w00 = (1.f - wy1) * (1.f - wx1) * msk;
    d.w01 = (1.f - wy1) * wx1 * msk;
    d.w10 = wy1 * (1.f - wx1) * msk;
    d.w11 = wy1 * wx1 * msk;
    if (!(((unsigned)y0 < (unsigned)Hh) & ((unsigned)x0 < (unsigned)Ww))) d.w00 = 0.f;
    if (!(((unsigned)y0 < (unsigned)Hh) & ((unsigned)x1 < (unsigned)Ww))) d.w01 = 0.f;
    if (!(((unsigned)y1 < (unsigned)Hh) & ((unsigned)x0 < (unsigned)Ww))) d.w10 = 0.f;
    if (!(((unsigned)y1 < (unsigned)Hh) & ((unsigned)x1 < (unsigned)Ww))) d.w11 = 0.f;
    const int y0c = min(max(y0, 0), Hh - 1);
    const int y1c = min(max(y1, 0), Hh - 1);
    const int x0c = min(max(x0, 0), Ww - 1);
    const int x1c = min(max(x1, 0), Ww - 1);
    d.i00 = y0c * Ww + x0c;  d.i01 = y0c * Ww + x1c;
    d.i10 = y1c * Ww + x0c;  d.i11 = y1c * Ww + x1c;
    return d;
}
__device__ __forceinline__ float samp(const Desc& d, const float* xc) {
    return d.w00 * __ldg(xc + d.i00) + d.w01 * __ldg(xc + d.i01)
         + d.w10 * __ldg(xc + d.i10) + d.w11 * __ldg(xc + d.i11);
}

#define PITCH  144     // W rows: 128B + 16B skew
#define TPITCH 272     // S^T rows (128 px): 256B + 16B skew

// Per-buffer layout (double-buffered S+W)
#define B_SHI 0                        // 64*272 = 17408
#define B_SLO (B_SHI + 64*TPITCH)
#define B_WHI (B_SLO + 64*TPITCH)      // 64*144 = 9216
#define B_WLO (B_WHI + 64*PITCH)
#define BUF_BYTES (B_WLO + 64*PITCH)   // 53248
#define T_TOTAL (2 * BUF_BYTES)        // 106496

// ---------------------------------------------------------------------------
// Kernel W-prep (unchanged)
// ---------------------------------------------------------------------------
#define WPREP_DCN (Kk*COUT*Cc)
#define WPREP_TOT (WPREP_DCN + Kk*OMPAD*Cc)
__global__ __launch_bounds__(256) void wprep_kernel(
    const float* __restrict__ w_dcn, const float* __restrict__ w_om)
{
    const int e = blockIdx.x * 256 + threadIdx.x;
    if (e >= WPREP_TOT) return;
    if (e < WPREP_DCN) {
        const int k = e / (COUT * Cc);
        const int r = e - k * (COUT * Cc);
        const int o = r >> 6;
        const int c = r & 63;
        const float w = __ldg(w_dcn + (size_t)o * CK + c * Kk + k);
        const __nv_bfloat16 hi = __float2bfloat16(w);
        g_whi[e] = __bfloat16_as_ushort(hi);
        g_wlo[e] = __bfloat16_as_ushort(__float2bfloat16(w - __bfloat162float(hi)));
    } else {
        const int e2 = e - WPREP_DCN;
        const int k = e2 >> 11;
        const int r = e2 & 2047;
        const int o = r >> 6;
        const int c = r & 63;
        float w = 0.f;
        if (o < 27) w = __ldg(w_om + (size_t)o * CK + c * Kk + k);
        const __nv_bfloat16 hi = __float2bfloat16(w);
        g_omhi[e2] = __bfloat16_as_ushort(hi);
        g_omlo[e2] = __bfloat16_as_ushort(__float2bfloat16(w - __bfloat162float(hi)));
    }
}

// ---------------------------------------------------------------------------
// Kernel A (HMMA): offset/mask conv. (round-7/9/10 version, ~36us)
// ---------------------------------------------------------------------------
#define CPITCH 144
__global__ __launch_bounds__(256, 3) void convA_mma_kernel(
    const float* __restrict__ x,
    const float* __restrict__ b_om)
{
    __shared__ char csm[128 * CPITCH * 2 + 32 * CPITCH * 2];  // 46080 B
#define CSHI 0
#define CSLO (128 * CPITCH)
#define CWHI (2 * 128 * CPITCH)
#define CWLO (2 * 128 * CPITCH + 32 * CPITCH)
    const uint32_t sbase = smem_u32(csm);
    const int n   = blockIdx.z;
    const int p   = blockIdx.x;
    const int tid = threadIdx.x;
    const int wid = tid >> 5;
    const int lid = tid & 31;

    const float* xn = x + (size_t)n * Cc * HW;

    float acc[4][4];
#pragma unroll
    for (int t = 0; t < 4; t++)
#pragma unroll
        for (int i = 0; i < 4; i++) acc[t][i] = 0.f;

    const int a_row  = wid * 16 + (((lid >> 3) & 1) << 3) + (lid & 7);
    const int a_cg   = (lid >> 4);
    const int b_oofs = ((lid >> 4) << 3) + (lid & 7);
    const int b_cg   = ((lid >> 3) & 1);

    const int g_row  = tid & 127;
    const int g_half = tid >> 7;

    for (int j = 0; j < 9; j++) {
        __syncthreads();
        {
            const uint32_t* whp = (const uint32_t*)g_omhi + j * 1024;
            const uint32_t* wlp = (const uint32_t*)g_omlo + j * 1024;
#pragma unroll
            for (int i = 0; i < 4; i++) {
                const int e  = tid + i * 256;
                const int o  = e >> 5;
                const int cg = e & 31;
                const uint32_t off = o * CPITCH + cg * 4;
                *(uint32_t*)(csm + CWHI + off) = __ldg(whp + e);
                *(uint32_t*)(csm + CWLO + off) = __ldg(wlp + e);
            }
        }
        {
            const int y  = p + j / 3 - 1;
            const int xc = g_row + j % 3 - 1;
            const bool ok = ((unsigned)y < (unsigned)Hh) & ((unsigned)xc < (unsigned)Ww);
            const float* bp = xn + (size_t)g_half * 32 * HW + y * Ww + xc;
            uint32_t soff = g_row * CPITCH + (g_half * 16) * 4;
#pragma unroll
            for (int i = 0; i < 16; i++) {
                const float v0 = ok ? __ldg(bp)      : 0.f;
                const float v1 = ok ? __ldg(bp + HW) : 0.f;
                bp += 2 * HW;
                uint32_t hi2, lo2;
                split_pack(v0, v1, hi2, lo2);
                *(uint32_t*)(csm + CSHI + soff) = hi2;
                *(uint32_t*)(csm + CSLO + soff) = lo2;
                soff += 4;
            }
        }
        __syncthreads();

#pragma unroll
        for (int ks = 0; ks < 4; ks++) {
            uint32_t ahi[4], alo[4];
            const uint32_t aoff = a_row * CPITCH + (ks * 2 + a_cg) * 16;
            ldsm_x4(ahi, sbase + CSHI + aoff);
            ldsm_x4(alo, sbase + CSLO + aoff);
#pragma unroll
            for (int nt = 0; nt < 2; nt++) {
                uint32_t bh[4], bl[4];
                const uint32_t boff = (nt * 16 + b_oofs) * CPITCH + (ks * 2 + b_cg) * 16;
                ldsm_x4(bh, sbase + CWHI + boff);
                ldsm_x4(bl, sbase + CWLO + boff);
                mma_bf16(acc[nt * 2],     ahi, bh);
                mma_bf16(acc[nt * 2 + 1], ahi, bh + 2);
                mma_bf16(acc[nt * 2],     ahi, bl);
                mma_bf16(acc[nt * 2 + 1], ahi, bl + 2);
                mma_bf16(acc[nt * 2],     alo, bh);
                mma_bf16(acc[nt * 2 + 1], alo, bh + 2);
            }
        }
    }

    const int px = p * Ww + wid * 16 + (lid >> 2);
    float* offp = g_off  + (size_t)n * OFFCH  * HW;
    float* mskp = g_mask + (size_t)n * MASKCH * HW;
#pragma unroll
    for (int t = 0; t < 4; t++) {
        const int o0 = t * 8 + 2 * (lid & 3);
#pragma unroll
        for (int i = 0; i < 4; i++) {
            const int o  = o0 + (i & 1);
            const int pq = px + (i >> 1) * 8;
            if (o >= 27) continue;
            const float v = acc[t][i] + __ldg(b_om + o);
            if (o < OFFCH) offp[(size_t)o * HW + pq] = v;
            else           mskp[(size_t)(o - OFFCH) * HW + pq] = 1.f / (1.f + expf(-v));
        }
    }
}

// ---------------------------------------------------------------------------
// Kernel BC: fused deform-sample + HMMA GEMM, WARP-SPECIALIZED.
//   128-px tile per CTA. Warps 0-3 = producers (gather+W stage),
//   warps 4-7 = consumers (MMA+epilogue). Double-buffered S+W.
//   Named barriers: FULL[b] = 1+b, EMPTY[b] = 3+b (count 256).
// ---------------------------------------------------------------------------
__global__ __launch_bounds__(256, 2) void fusedBC_mma_kernel(
    const float* __restrict__ x,
    float* __restrict__ out)
{
    extern __shared__ char smem[];
    const uint32_t sbase0 = smem_u32(smem);
    const int n   = blockIdx.z;
    const int j0  = blockIdx.x * 128;      // this CTA's 128 pixels
    const int tid = threadIdx.x;
    const int lid = tid & 31;

    const float* xn = x + (size_t)n * Cc * HW;

    if (tid < 128) {
        // ================= PRODUCER (warps 0-3) =================
        const int pp  = tid & 63;          // pixels 2pp, 2pp+1
        const int ckh = tid >> 6;          // 0/1 -> channels ckh*32..+31

        for (int j = 0; j < 9; j++) {
            const int b = j & 1;
            char* gs = smem + b * BUF_BYTES;
            if (j >= 2) BAR_SYNC(3 + b, 256);       // buffer b free
            // stage W chunk j
            {
                const uint32_t* whp = (const uint32_t*)g_whi + j * 2048;
                const uint32_t* wlp = (const uint32_t*)g_wlo + j * 2048;
#pragma unroll
                for (int i = 0; i < 16; i++) {
                    const int e  = tid + i * 128;
                    const int o  = e >> 5;
                    const int cg = e & 31;
                    const uint32_t off = o * PITCH + cg * 4;
                    *(uint32_t*)(gs + B_WHI + off) = __ldg(whp + e);
                    *(uint32_t*)(gs + B_WLO + off) = __ldg(wlp + e);
                }
            }
            // gather S chunk j
            const Desc d0 = make_sdesc(n, j, j0 + 2 * pp);
            const Desc d1 = make_sdesc(n, j, j0 + 2 * pp + 1);
            {
                const float* xc = xn + (size_t)(ckh * 32) * HW;
                uint32_t soff = (ckh * 32) * TPITCH + pp * 4;
#pragma unroll 8
                for (int i = 0; i < 32; i++) {
                    const float v0 = samp(d0, xc);
                    const float v1 = samp(d1, xc);
                    xc += HW;
                    uint32_t hi2, lo2;
                    split_pack(v0, v1, hi2, lo2);
                    *(uint32_t*)(gs + B_SHI + soff) = hi2;
                    *(uint32_t*)(gs + B_SLO + soff) = lo2;
                    soff += TPITCH;
                }
            }
            BAR_ARRIVE(1 + b, 256);                 // buffer b full
        }
    } else {
        // ================= CONSUMER (warps 4-7) =================
        const int cw = (tid >> 5) - 4;     // 0..3, owns 32 px

        float acc[2][8][4];
#pragma unroll
        for (int m = 0; m < 2; m++)
#pragma unroll
            for (int t = 0; t < 8; t++)
#pragma unroll
                for (int i = 0; i < 4; i++) acc[m][t][i] = 0.f;

        const int a_ckb = (lid & 7) + (((lid >> 3) & 2) << 2);
        const int a_px8 = (((lid >> 3) & 1) << 3);
        const int b_oofs = ((lid >> 4) << 3) + (lid & 7);
        const int b_cg   = ((lid >> 3) & 1);

        for (int j = 0; j < 9; j++) {
            const int b = j & 1;
            const uint32_t sb = sbase0 + b * BUF_BYTES;
            BAR_SYNC(1 + b, 256);                   // buffer b full

#pragma unroll
            for (int ks = 0; ks < 4; ks++) {
                uint32_t ahi[2][4], alo[2][4];
#pragma unroll
                for (int m = 0; m < 2; m++) {
                    const uint32_t aoff = (ks * 16 + a_ckb) * TPITCH
                                        + (cw * 32 + m * 16 + a_px8) * 2;
                    ldsm_x4_t(ahi[m], sb + B_SHI + aoff);
                    ldsm_x4_t(alo[m], sb + B_SLO + aoff);
                }
#pragma unroll
                for (int nt = 0; nt < 4; nt++) {
                    uint32_t bh[4], bl[4];
                    const uint32_t boff = (nt * 16 + b_oofs) * PITCH
                                        + (ks * 2 + b_cg) * 16;
                    ldsm_x4(bh, sb + B_WHI + boff);
                    ldsm_x4(bl, sb + B_WLO + boff);
#pragma unroll
                    for (int m = 0; m < 2; m++) {
                        mma_bf16(acc[m][nt * 2],     ahi[m], bh);
                        mma_bf16(acc[m][nt * 2 + 1], ahi[m], bh + 2);
                        mma_bf16(acc[m][nt * 2],     ahi[m], bl);
                        mma_bf16(acc[m][nt * 2 + 1], ahi[m], bl + 2);
                        mma_bf16(acc[m][nt * 2],     alo[m], bh);
                        mma_bf16(acc[m][nt * 2 + 1], alo[m], bh + 2);
                    }
                }
            }
            if (j < 7) BAR_ARRIVE(3 + b, 256);      // buffer b free
        }

        // Epilogue
        float* op = out + (size_t)n * COUT * HW;
#pragma unroll
        for (int m = 0; m < 2; m++) {
            const int px = j0 + cw * 32 + m * 16 + (lid >> 2);
#pragma unroll
            for (int t = 0; t < 8; t++) {
                const int o0 = t * 8 + 2 * (lid & 3);
                op[(size_t)o0       * HW + px    ] = acc[m][t][0];
                op[(size_t)(o0 + 1) * HW + px    ] = acc[m][t][1];
                op[(size_t)o0       * HW + px + 8] = acc[m][t][2];
                op[(size_t)(o0 + 1) * HW + px + 8] = acc[m][t][3];
            }
        }
    }
}

// ---------------------------------------------------------------------------
extern "C" void kernel_launch(void* const* d_in, const int* in_sizes, int n_in,
                              void* d_out, int out_size)
{
    const float* x     = (const float*)d_in[0];  // (4,64,128,128)
    const float* w_om  = (const float*)d_in[1];  // (27,64,3,3)
    const float* b_om  = (const float*)d_in[2];  // (27,)
    const float* w_dcn = (const float*)d_in[3];  // (64,64,3,3)
    float* out = (float*)d_out;                  // (4,64,128,128)

    wprep_kernel<<<(WPREP_TOT + 255) / 256, 256>>>(w_dcn, w_om);

    dim3 gA(Hh, 1, Nn);                          // 512 blocks
    convA_mma_kernel<<<gA, 256>>>(x, b_om);

    cudaFuncSetAttribute(fusedBC_mma_kernel,
                         cudaFuncAttributeMaxDynamicSharedMemorySize, T_TOTAL);
    dim3 gBC(HW / 128, 1, Nn);                   // 128 x 4 = 512 blocks
    fusedBC_mma_kernel<<<gBC, 256, T_TOTAL>>>(x, out);
}